// round 10
// baseline (speedup 1.0000x reference)
#include <cuda_runtime.h>
#include <cstdint>

#define NN 100000
#define NE 1600000
#define IN_CH 64
#define HID 64
#define N_CLS 40

// Scratch (allocation-free contract: __device__ globals).
__device__ float4 g_Y4 [(size_t)NN * (HID / 4)];
__device__ float4 g_H14[(size_t)NN * (HID / 4)];
__device__ float4 g_Z4 [(size_t)NN * (HID / 4)];
__device__ int    g_cnt [NN];      // out-degree histogram (by src)
__device__ int    g_ptr [NN + 1];  // CSC row pointers (grouped by src)
__device__ int    g_woff[NN];      // working offsets for fill
__device__ int    g_cdst[NE];      // dst node per edge, grouped by src
__device__ int    g_deg [NN];      // in-degree (by dst), for bias term

// ---------------------------------------------------------------------------
// Zero: H1, Z (float4), deg, cnt
// ---------------------------------------------------------------------------
__global__ void __launch_bounds__(256) zero_kernel(int n) {
    int t = blockIdx.x * blockDim.x + threadIdx.x;
    int nf4 = n * (HID / 4);
    float4 z4 = make_float4(0.f, 0.f, 0.f, 0.f);
    if (t < nf4) {
        g_H14[t] = z4;
    } else if (t < 2 * nf4) {
        g_Z4[t - nf4] = z4;
    }
    if (t < n) { g_deg[t] = 0; g_cnt[t] = 0; }
}

// Histogram of src indices
__global__ void __launch_bounds__(256) hist_kernel(const int* __restrict__ ei, int E) {
    int e = blockIdx.x * blockDim.x + threadIdx.x;
    if (e < E) atomicAdd(&g_cnt[__ldg(ei + e)], 1);
}

// Single-block exclusive scan of g_cnt -> g_ptr (and g_woff), g_ptr[n]=E
__global__ void __launch_bounds__(1024) scan_kernel(int n) {
    __shared__ int sh[1024];
    int tid = threadIdx.x;
    int chunk = (n + 1023) / 1024;
    int begin = tid * chunk;
    int end = min(begin + chunk, n);

    int s = 0;
    for (int i = begin; i < end; i++) s += g_cnt[i];

    sh[tid] = s;
    __syncthreads();
    for (int off = 1; off < 1024; off <<= 1) {
        int v = (tid >= off) ? sh[tid - off] : 0;
        __syncthreads();
        sh[tid] += v;
        __syncthreads();
    }
    int run = sh[tid] - s;

    for (int i = begin; i < end; i++) {
        g_ptr[i] = run;
        g_woff[i] = run;
        run += g_cnt[i];
    }
    if (tid == 1023) g_ptr[n] = run;
}

// CSC fill: slot per src via atomic bump; store dst
__global__ void __launch_bounds__(256) fill_kernel(const int* __restrict__ ei, int E) {
    int e = blockIdx.x * blockDim.x + threadIdx.x;
    if (e >= E) return;
    int s = __ldg(ei + e);
    int d = __ldg(ei + E + e);
    int pos = atomicAdd(&g_woff[s], 1);
    g_cdst[pos] = d;
}

// ---------------------------------------------------------------------------
// Dense layer 1: Y = relu(NF @ W1 + b1), thread-per-row, W1 in smem
// ---------------------------------------------------------------------------
__global__ void __launch_bounds__(256) dense1_kernel(
    const float* __restrict__ nf, const float* __restrict__ W1,
    const float* __restrict__ b1, int n)
{
    __shared__ float Ws[IN_CH * HID];
    __shared__ float bs[HID];
    for (int i = threadIdx.x; i < IN_CH * HID; i += blockDim.x) Ws[i] = W1[i];
    for (int i = threadIdx.x; i < HID; i += blockDim.x) bs[i] = b1[i];
    __syncthreads();

    int row = blockIdx.x * blockDim.x + threadIdx.x;
    if (row >= n) return;

    float x[IN_CH];
    const float4* xr = reinterpret_cast<const float4*>(nf + (size_t)row * IN_CH);
    #pragma unroll
    for (int k4 = 0; k4 < IN_CH / 4; k4++) {
        float4 v = xr[k4];
        x[4*k4+0] = v.x; x[4*k4+1] = v.y; x[4*k4+2] = v.z; x[4*k4+3] = v.w;
    }

    float4* yr = g_Y4 + (size_t)row * (HID / 4);
    #pragma unroll 1
    for (int jj = 0; jj < HID / 4; jj++) {
        float4 acc = *reinterpret_cast<const float4*>(bs + jj * 4);
        #pragma unroll
        for (int k = 0; k < IN_CH; k++) {
            float4 w = *reinterpret_cast<const float4*>(Ws + k * HID + jj * 4);
            acc.x = fmaf(x[k], w.x, acc.x);
            acc.y = fmaf(x[k], w.y, acc.y);
            acc.z = fmaf(x[k], w.z, acc.z);
            acc.w = fmaf(x[k], w.w, acc.w);
        }
        acc.x = fmaxf(acc.x, 0.f); acc.y = fmaxf(acc.y, 0.f);
        acc.z = fmaxf(acc.z, 0.f); acc.w = fmaxf(acc.w, 0.f);
        yr[jj] = acc;
    }
}

// ---------------------------------------------------------------------------
// Push-style scatter: half-warp per SRC node. Load the src row ONCE into
// registers (lane c of 16 holds float4 chunk c), then stream
// red.global.add.v4.f32 to each out-neighbor's row. REDs are fire-and-forget;
// dst-index loads are independent -> pipelined via unroll. Src-row read
// traffic drops 410MB -> 25.6MB per pass vs edge-parallel gather+RED.
// PASS==0: Y -> H1 (+ in-degree);  PASS==1: H1 -> Z
// ---------------------------------------------------------------------------
template <int PASS>
__global__ void __launch_bounds__(256) push_kernel(int n)
{
    int warp = (blockIdx.x * blockDim.x + threadIdx.x) >> 5;
    int lane = threadIdx.x & 31;
    int half = lane >> 4;
    int c    = lane & 15;
    int node = warp * 2 + half;
    if (node >= n) return;

    int beg = __ldg(&g_ptr[node]);
    int end = __ldg(&g_ptr[node + 1]);
    if (beg == end) return;

    const float4* srct = (PASS == 0) ? g_Y4  : g_H14;
    float4*       dstt = (PASS == 0) ? g_H14 : g_Z4;

    float4 v = __ldg(&srct[(size_t)node * (HID / 4) + c]);

    int e = beg;
    for (; e + 3 < end; e += 4) {
        int d0 = __ldg(&g_cdst[e]);
        int d1 = __ldg(&g_cdst[e + 1]);
        int d2 = __ldg(&g_cdst[e + 2]);
        int d3 = __ldg(&g_cdst[e + 3]);
        unsigned long long p0 = (unsigned long long)__cvta_generic_to_global(dstt + (size_t)d0 * (HID / 4) + c);
        unsigned long long p1 = (unsigned long long)__cvta_generic_to_global(dstt + (size_t)d1 * (HID / 4) + c);
        unsigned long long p2 = (unsigned long long)__cvta_generic_to_global(dstt + (size_t)d2 * (HID / 4) + c);
        unsigned long long p3 = (unsigned long long)__cvta_generic_to_global(dstt + (size_t)d3 * (HID / 4) + c);
        asm volatile("red.global.add.v4.f32 [%0], {%1, %2, %3, %4};" :: "l"(p0), "f"(v.x), "f"(v.y), "f"(v.z), "f"(v.w) : "memory");
        asm volatile("red.global.add.v4.f32 [%0], {%1, %2, %3, %4};" :: "l"(p1), "f"(v.x), "f"(v.y), "f"(v.z), "f"(v.w) : "memory");
        asm volatile("red.global.add.v4.f32 [%0], {%1, %2, %3, %4};" :: "l"(p2), "f"(v.x), "f"(v.y), "f"(v.z), "f"(v.w) : "memory");
        asm volatile("red.global.add.v4.f32 [%0], {%1, %2, %3, %4};" :: "l"(p3), "f"(v.x), "f"(v.y), "f"(v.z), "f"(v.w) : "memory");
        if (PASS == 0 && c == 0) {
            atomicAdd(&g_deg[d0], 1); atomicAdd(&g_deg[d1], 1);
            atomicAdd(&g_deg[d2], 1); atomicAdd(&g_deg[d3], 1);
        }
    }
    for (; e < end; e++) {
        int d0 = __ldg(&g_cdst[e]);
        unsigned long long p0 = (unsigned long long)__cvta_generic_to_global(dstt + (size_t)d0 * (HID / 4) + c);
        asm volatile("red.global.add.v4.f32 [%0], {%1, %2, %3, %4};" :: "l"(p0), "f"(v.x), "f"(v.y), "f"(v.z), "f"(v.w) : "memory");
        if (PASS == 0 && c == 0) atomicAdd(&g_deg[d0], 1);
    }
}

// ---------------------------------------------------------------------------
// Fused dense tail: h2 = Z@W2 + deg*b2; logits = h2@Wf + bf; softmax -> out
// ---------------------------------------------------------------------------
__global__ void __launch_bounds__(128) dense2_kernel(
    const float* __restrict__ W2, const float* __restrict__ b2,
    const float* __restrict__ Wf, const float* __restrict__ bf,
    float* __restrict__ out, int n)
{
    __shared__ float W2s[HID * HID];
    __shared__ float Wfs[HID * N_CLS];
    __shared__ float b2s[HID];
    __shared__ float bfs[N_CLS];
    for (int i = threadIdx.x; i < HID * HID; i += blockDim.x) W2s[i] = W2[i];
    for (int i = threadIdx.x; i < HID * N_CLS; i += blockDim.x) Wfs[i] = Wf[i];
    for (int i = threadIdx.x; i < HID; i += blockDim.x) b2s[i] = b2[i];
    for (int i = threadIdx.x; i < N_CLS; i += blockDim.x) bfs[i] = bf[i];
    __syncthreads();

    int row = blockIdx.x * blockDim.x + threadIdx.x;
    if (row >= n) return;

    float z[HID];
    const float4* zr = g_Z4 + (size_t)row * (HID / 4);
    #pragma unroll
    for (int k4 = 0; k4 < HID / 4; k4++) {
        float4 v = zr[k4];
        z[4*k4+0] = v.x; z[4*k4+1] = v.y; z[4*k4+2] = v.z; z[4*k4+3] = v.w;
    }
    float degf = (float)__ldg(&g_deg[row]);

    float logits[N_CLS];
    #pragma unroll
    for (int cc = 0; cc < N_CLS; cc++) logits[cc] = bfs[cc];

    #pragma unroll 1
    for (int jj = 0; jj < HID / 4; jj++) {
        float h[4];
        #pragma unroll
        for (int u = 0; u < 4; u++) h[u] = degf * b2s[jj * 4 + u];
        #pragma unroll
        for (int k = 0; k < HID; k++) {
            float4 w = *reinterpret_cast<const float4*>(W2s + k * HID + jj * 4);
            h[0] = fmaf(z[k], w.x, h[0]);
            h[1] = fmaf(z[k], w.y, h[1]);
            h[2] = fmaf(z[k], w.z, h[2]);
            h[3] = fmaf(z[k], w.w, h[3]);
        }
        #pragma unroll
        for (int u = 0; u < 4; u++) {
            int j = jj * 4 + u;
            #pragma unroll
            for (int c4 = 0; c4 < N_CLS / 4; c4++) {
                float4 w = *reinterpret_cast<const float4*>(Wfs + j * N_CLS + c4 * 4);
                logits[c4*4+0] = fmaf(h[u], w.x, logits[c4*4+0]);
                logits[c4*4+1] = fmaf(h[u], w.y, logits[c4*4+1]);
                logits[c4*4+2] = fmaf(h[u], w.z, logits[c4*4+2]);
                logits[c4*4+3] = fmaf(h[u], w.w, logits[c4*4+3]);
            }
        }
    }

    float m = logits[0];
    #pragma unroll
    for (int cc = 1; cc < N_CLS; cc++) m = fmaxf(m, logits[cc]);
    float ssum = 0.f;
    #pragma unroll
    for (int cc = 0; cc < N_CLS; cc++) {
        float ev = __expf(logits[cc] - m);
        logits[cc] = ev;
        ssum += ev;
    }
    float inv = 1.f / ssum;
    float* orow = out + (size_t)row * N_CLS;
    #pragma unroll
    for (int c4 = 0; c4 < N_CLS / 4; c4++) {
        float4 o;
        o.x = logits[c4*4+0] * inv; o.y = logits[c4*4+1] * inv;
        o.z = logits[c4*4+2] * inv; o.w = logits[c4*4+3] * inv;
        *reinterpret_cast<float4*>(orow + c4 * 4) = o;
    }
}

// ---------------------------------------------------------------------------
extern "C" void kernel_launch(void* const* d_in, const int* in_sizes, int n_in,
                              void* d_out, int out_size)
{
    const float* nf = (const float*)d_in[0];
    const int*   ei = (const int*)d_in[1];   // int32 (JAX x64 disabled)
    const float* W1 = (const float*)d_in[2];
    const float* b1 = (const float*)d_in[3];
    const float* W2 = (const float*)d_in[4];
    const float* b2 = (const float*)d_in[5];
    const float* Wf = (const float*)d_in[6];
    const float* bf = (const float*)d_in[7];
    float* out = (float*)d_out;

    int n = in_sizes[0] / IN_CH;   // 100000
    int E = in_sizes[1] / 2;       // 1600000

    int nf4 = n * (HID / 4);
    zero_kernel<<<(2 * nf4 + 255) / 256, 256>>>(n);       // H1, Z, deg, cnt
    hist_kernel<<<(E + 255) / 256, 256>>>(ei, E);          // out-degree by src
    scan_kernel<<<1, 1024>>>(n);
    fill_kernel<<<(E + 255) / 256, 256>>>(ei, E);          // CSC: dst grouped by src
    dense1_kernel<<<(n + 255) / 256, 256>>>(nf, W1, b1, n);

    // Push passes: half-warp per src node, row in regs, REDs to neighbors
    int pblocks = (((n + 1) / 2) * 32 + 255) / 256;
    push_kernel<0><<<pblocks, 256>>>(n);
    push_kernel<1><<<pblocks, 256>>>(n);

    dense2_kernel<<<(n + 127) / 128, 128>>>(W2, b2, Wf, bf, out, n);
}

// round 11
// speedup vs baseline: 1.4215x; 1.4215x over previous
#include <cuda_runtime.h>
#include <cstdint>

#define NN 100000
#define IN_CH 64
#define HID 64
#define N_CLS 40

// Scratch (allocation-free contract: __device__ globals).
// float4 => 16B-aligned base, required by red.global.add.v4.f32.
__device__ float4 g_Y4 [(size_t)NN * (HID / 4)];
__device__ float4 g_H14[(size_t)NN * (HID / 4)];
__device__ float4 g_Z4 [(size_t)NN * (HID / 4)];
__device__ int    g_deg[NN];

// ---------------------------------------------------------------------------
// Zero scratch: H1, Z (float4 granularity) and deg
// ---------------------------------------------------------------------------
__global__ void __launch_bounds__(256) zero_kernel(int n) {
    int t = blockIdx.x * blockDim.x + threadIdx.x;
    int nf4 = n * (HID / 4);
    float4 z4 = make_float4(0.f, 0.f, 0.f, 0.f);
    if (t < nf4) {
        g_H14[t] = z4;
    } else if (t < 2 * nf4) {
        g_Z4[t - nf4] = z4;
    }
    if (t < n) g_deg[t] = 0;
}

// ---------------------------------------------------------------------------
// Dense layer 1: Y = relu(NF @ W1 + b1), thread-per-row, W1 in smem
// ---------------------------------------------------------------------------
__global__ void __launch_bounds__(256) dense1_kernel(
    const float* __restrict__ nf, const float* __restrict__ W1,
    const float* __restrict__ b1, int n)
{
    __shared__ float Ws[IN_CH * HID];
    __shared__ float bs[HID];
    for (int i = threadIdx.x; i < IN_CH * HID; i += blockDim.x) Ws[i] = W1[i];
    for (int i = threadIdx.x; i < HID; i += blockDim.x) bs[i] = b1[i];
    __syncthreads();

    int row = blockIdx.x * blockDim.x + threadIdx.x;
    if (row >= n) return;

    float x[IN_CH];
    const float4* xr = reinterpret_cast<const float4*>(nf + (size_t)row * IN_CH);
    #pragma unroll
    for (int k4 = 0; k4 < IN_CH / 4; k4++) {
        float4 v = xr[k4];
        x[4*k4+0] = v.x; x[4*k4+1] = v.y; x[4*k4+2] = v.z; x[4*k4+3] = v.w;
    }

    float4* yr = g_Y4 + (size_t)row * (HID / 4);
    #pragma unroll 1
    for (int jj = 0; jj < HID / 4; jj++) {
        float4 acc = *reinterpret_cast<const float4*>(bs + jj * 4);
        #pragma unroll
        for (int k = 0; k < IN_CH; k++) {
            float4 w = *reinterpret_cast<const float4*>(Ws + k * HID + jj * 4);
            acc.x = fmaf(x[k], w.x, acc.x);
            acc.y = fmaf(x[k], w.y, acc.y);
            acc.z = fmaf(x[k], w.z, acc.z);
            acc.w = fmaf(x[k], w.w, acc.w);
        }
        acc.x = fmaxf(acc.x, 0.f); acc.y = fmaxf(acc.y, 0.f);
        acc.z = fmaxf(acc.z, 0.f); acc.w = fmaxf(acc.w, 0.f);
        yr[jj] = acc;
    }
}

// ---------------------------------------------------------------------------
// Edge-parallel scatter-add, LSU-slim version.
// One warp = 2 edges (half-warp each, 16 lanes x float4 chunk).
// Only lanes 0 and 16 load the (src,dst) index pair for their edge; values
// are broadcast to the half-warp via shfl (ALU pipe), cutting redundant
// index LDGs 32 -> 2 per edge. Row move stays LDG.128 + RED.128 per lane.
// PASS==0: Y -> H1 (+ in-degree via fire-and-forget red.u32)
// PASS==1: H1 -> Z
// ---------------------------------------------------------------------------
template <int PASS>
__global__ void __launch_bounds__(256) scatter_kernel(
    const int* __restrict__ ei, int E)
{
    long long tid = (long long)blockIdx.x * blockDim.x + threadIdx.x;
    int wrp  = (int)(tid >> 5);
    int lane = (int)(tid & 31);
    int half = lane >> 4;
    int c    = lane & 15;

    long long e = (long long)wrp * 2 + half;
    bool valid = (e < E);

    int sl = 0, dl = 0;
    if (c == 0 && valid) {
        sl = __ldg(ei + e);
        dl = __ldg(ei + E + e);
    }
    int s = __shfl_sync(0xffffffffu, sl, half << 4);
    int d = __shfl_sync(0xffffffffu, dl, half << 4);
    if (!valid) return;

    const float4* srct = (PASS == 0) ? g_Y4  : g_H14;
    float4*       dstt = (PASS == 0) ? g_H14 : g_Z4;

    float4 v = __ldg(&srct[(size_t)s * (HID / 4) + c]);
    float4* p = dstt + (size_t)d * (HID / 4) + c;
    unsigned long long gp = (unsigned long long)__cvta_generic_to_global(p);
    asm volatile("red.global.add.v4.f32 [%0], {%1, %2, %3, %4};"
                 :: "l"(gp), "f"(v.x), "f"(v.y), "f"(v.z), "f"(v.w)
                 : "memory");

    if (PASS == 0 && c == 0) {
        unsigned long long dp = (unsigned long long)__cvta_generic_to_global(&g_deg[d]);
        asm volatile("red.global.add.u32 [%0], %1;" :: "l"(dp), "r"(1) : "memory");
    }
}

// ---------------------------------------------------------------------------
// Fused dense tail: h2 = Z@W2 + deg*b2; logits = h2@Wf + bf; softmax -> out
// ---------------------------------------------------------------------------
__global__ void __launch_bounds__(128) dense2_kernel(
    const float* __restrict__ W2, const float* __restrict__ b2,
    const float* __restrict__ Wf, const float* __restrict__ bf,
    float* __restrict__ out, int n)
{
    __shared__ float W2s[HID * HID];
    __shared__ float Wfs[HID * N_CLS];
    __shared__ float b2s[HID];
    __shared__ float bfs[N_CLS];
    for (int i = threadIdx.x; i < HID * HID; i += blockDim.x) W2s[i] = W2[i];
    for (int i = threadIdx.x; i < HID * N_CLS; i += blockDim.x) Wfs[i] = Wf[i];
    for (int i = threadIdx.x; i < HID; i += blockDim.x) b2s[i] = b2[i];
    for (int i = threadIdx.x; i < N_CLS; i += blockDim.x) bfs[i] = bf[i];
    __syncthreads();

    int row = blockIdx.x * blockDim.x + threadIdx.x;
    if (row >= n) return;

    float z[HID];
    const float4* zr = g_Z4 + (size_t)row * (HID / 4);
    #pragma unroll
    for (int k4 = 0; k4 < HID / 4; k4++) {
        float4 v = zr[k4];
        z[4*k4+0] = v.x; z[4*k4+1] = v.y; z[4*k4+2] = v.z; z[4*k4+3] = v.w;
    }
    float degf = (float)__ldg(&g_deg[row]);

    float logits[N_CLS];
    #pragma unroll
    for (int cc = 0; cc < N_CLS; cc++) logits[cc] = bfs[cc];

    #pragma unroll 1
    for (int jj = 0; jj < HID / 4; jj++) {
        float h[4];
        #pragma unroll
        for (int u = 0; u < 4; u++) h[u] = degf * b2s[jj * 4 + u];
        #pragma unroll
        for (int k = 0; k < HID; k++) {
            float4 w = *reinterpret_cast<const float4*>(W2s + k * HID + jj * 4);
            h[0] = fmaf(z[k], w.x, h[0]);
            h[1] = fmaf(z[k], w.y, h[1]);
            h[2] = fmaf(z[k], w.z, h[2]);
            h[3] = fmaf(z[k], w.w, h[3]);
        }
        #pragma unroll
        for (int u = 0; u < 4; u++) {
            int j = jj * 4 + u;
            #pragma unroll
            for (int c4 = 0; c4 < N_CLS / 4; c4++) {
                float4 w = *reinterpret_cast<const float4*>(Wfs + j * N_CLS + c4 * 4);
                logits[c4*4+0] = fmaf(h[u], w.x, logits[c4*4+0]);
                logits[c4*4+1] = fmaf(h[u], w.y, logits[c4*4+1]);
                logits[c4*4+2] = fmaf(h[u], w.z, logits[c4*4+2]);
                logits[c4*4+3] = fmaf(h[u], w.w, logits[c4*4+3]);
            }
        }
    }

    float m = logits[0];
    #pragma unroll
    for (int cc = 1; cc < N_CLS; cc++) m = fmaxf(m, logits[cc]);
    float ssum = 0.f;
    #pragma unroll
    for (int cc = 0; cc < N_CLS; cc++) {
        float ev = __expf(logits[cc] - m);
        logits[cc] = ev;
        ssum += ev;
    }
    float inv = 1.f / ssum;
    float* orow = out + (size_t)row * N_CLS;
    #pragma unroll
    for (int c4 = 0; c4 < N_CLS / 4; c4++) {
        float4 o;
        o.x = logits[c4*4+0] * inv; o.y = logits[c4*4+1] * inv;
        o.z = logits[c4*4+2] * inv; o.w = logits[c4*4+3] * inv;
        *reinterpret_cast<float4*>(orow + c4 * 4) = o;
    }
}

// ---------------------------------------------------------------------------
extern "C" void kernel_launch(void* const* d_in, const int* in_sizes, int n_in,
                              void* d_out, int out_size)
{
    const float* nf = (const float*)d_in[0];
    const int*   ei = (const int*)d_in[1];   // int32 (JAX x64 disabled)
    const float* W1 = (const float*)d_in[2];
    const float* b1 = (const float*)d_in[3];
    const float* W2 = (const float*)d_in[4];
    const float* b2 = (const float*)d_in[5];
    const float* Wf = (const float*)d_in[6];
    const float* bf = (const float*)d_in[7];
    float* out = (float*)d_out;

    int n = in_sizes[0] / IN_CH;   // 100000
    int E = in_sizes[1] / 2;       // 1600000

    int nf4 = n * (HID / 4);
    zero_kernel<<<(2 * nf4 + 255) / 256, 256>>>(n);
    dense1_kernel<<<(n + 255) / 256, 256>>>(nf, W1, b1, n);

    // warp = 2 edges -> threads = ceil(E/2)*32
    long long warps = ((long long)E + 1) / 2;
    long long threads = warps * 32;
    int sblocks = (int)((threads + 255) / 256);
    scatter_kernel<0><<<sblocks, 256>>>(ei, E);
    scatter_kernel<1><<<sblocks, 256>>>(ei, E);

    dense2_kernel<<<(n + 127) / 128, 128>>>(W2, b2, Wf, bf, out, n);
}

// round 12
// speedup vs baseline: 1.4396x; 1.0127x over previous
#include <cuda_runtime.h>
#include <cstdint>

#define NN 100000
#define IN_CH 64
#define HID 64
#define N_CLS 40

// Scratch (allocation-free contract: __device__ globals).
// float4 => 16B-aligned base, required by red.global.add.v4.f32.
__device__ float4 g_Y4 [(size_t)NN * (HID / 4)];
__device__ float4 g_H14[(size_t)NN * (HID / 4)];
__device__ float4 g_Z4 [(size_t)NN * (HID / 4)];
__device__ int    g_deg[NN];

// ---------------------------------------------------------------------------
// Dense layer 1 + fused scratch zeroing.
// Y = relu(NF @ W1 + b1), thread-per-row, W1 in smem.
// Each thread also zeroes its H1 row, Z row and deg entry (replaces the
// standalone zero pass; completes before scatter<0> launches).
// ---------------------------------------------------------------------------
__global__ void __launch_bounds__(256) dense1_kernel(
    const float* __restrict__ nf, const float* __restrict__ W1,
    const float* __restrict__ b1, int n)
{
    __shared__ float Ws[IN_CH * HID];
    __shared__ float bs[HID];
    for (int i = threadIdx.x; i < IN_CH * HID; i += blockDim.x) Ws[i] = W1[i];
    for (int i = threadIdx.x; i < HID; i += blockDim.x) bs[i] = b1[i];
    __syncthreads();

    int row = blockIdx.x * blockDim.x + threadIdx.x;
    if (row >= n) return;

    // zero scratch owned by this row
    {
        float4 z4 = make_float4(0.f, 0.f, 0.f, 0.f);
        float4* h1r = g_H14 + (size_t)row * (HID / 4);
        float4* zr  = g_Z4  + (size_t)row * (HID / 4);
        #pragma unroll
        for (int j = 0; j < HID / 4; j++) { h1r[j] = z4; zr[j] = z4; }
        g_deg[row] = 0;
    }

    float x[IN_CH];
    const float4* xr = reinterpret_cast<const float4*>(nf + (size_t)row * IN_CH);
    #pragma unroll
    for (int k4 = 0; k4 < IN_CH / 4; k4++) {
        float4 v = xr[k4];
        x[4*k4+0] = v.x; x[4*k4+1] = v.y; x[4*k4+2] = v.z; x[4*k4+3] = v.w;
    }

    float4* yr = g_Y4 + (size_t)row * (HID / 4);
    #pragma unroll 1
    for (int jj = 0; jj < HID / 4; jj++) {
        float4 acc = *reinterpret_cast<const float4*>(bs + jj * 4);
        #pragma unroll
        for (int k = 0; k < IN_CH; k++) {
            float4 w = *reinterpret_cast<const float4*>(Ws + k * HID + jj * 4);
            acc.x = fmaf(x[k], w.x, acc.x);
            acc.y = fmaf(x[k], w.y, acc.y);
            acc.z = fmaf(x[k], w.z, acc.z);
            acc.w = fmaf(x[k], w.w, acc.w);
        }
        acc.x = fmaxf(acc.x, 0.f); acc.y = fmaxf(acc.y, 0.f);
        acc.z = fmaxf(acc.z, 0.f); acc.w = fmaxf(acc.w, 0.f);
        yr[jj] = acc;
    }
}

// ---------------------------------------------------------------------------
// Edge-parallel scatter-add (exact round-4 form — fastest measured).
// 16 threads per edge, each moving one float4 via vector red.global.
// PASS==0: Y -> H1 (+ degree histogram);  PASS==1: H1 -> Z
// ---------------------------------------------------------------------------
template <int PASS>
__global__ void __launch_bounds__(256) scatter_kernel(
    const int* __restrict__ ei, int E)
{
    long long tid = (long long)blockIdx.x * blockDim.x + threadIdx.x;
    int e = (int)(tid >> 4);
    if (e >= E) return;
    int c = (int)(tid & 15);

    int s = __ldg(ei + e);
    int d = __ldg(ei + E + e);

    const float4* srct = (PASS == 0) ? g_Y4  : g_H14;
    float4*       dstt = (PASS == 0) ? g_H14 : g_Z4;

    float4 v = __ldg(&srct[(size_t)s * (HID / 4) + c]);
    float4* p = dstt + (size_t)d * (HID / 4) + c;
    unsigned long long gp = (unsigned long long)__cvta_generic_to_global(p);
    asm volatile("red.global.add.v4.f32 [%0], {%1, %2, %3, %4};"
                 :: "l"(gp), "f"(v.x), "f"(v.y), "f"(v.z), "f"(v.w)
                 : "memory");

    if (PASS == 0 && c == 0) atomicAdd(&g_deg[d], 1);
}

// ---------------------------------------------------------------------------
// Fused dense tail: h2 = Z@W2 + deg*b2; logits = h2@Wf + bf; softmax -> out
// ---------------------------------------------------------------------------
__global__ void __launch_bounds__(128) dense2_kernel(
    const float* __restrict__ W2, const float* __restrict__ b2,
    const float* __restrict__ Wf, const float* __restrict__ bf,
    float* __restrict__ out, int n)
{
    __shared__ float W2s[HID * HID];
    __shared__ float Wfs[HID * N_CLS];
    __shared__ float b2s[HID];
    __shared__ float bfs[N_CLS];
    for (int i = threadIdx.x; i < HID * HID; i += blockDim.x) W2s[i] = W2[i];
    for (int i = threadIdx.x; i < HID * N_CLS; i += blockDim.x) Wfs[i] = Wf[i];
    for (int i = threadIdx.x; i < HID; i += blockDim.x) b2s[i] = b2[i];
    for (int i = threadIdx.x; i < N_CLS; i += blockDim.x) bfs[i] = bf[i];
    __syncthreads();

    int row = blockIdx.x * blockDim.x + threadIdx.x;
    if (row >= n) return;

    float z[HID];
    const float4* zr = g_Z4 + (size_t)row * (HID / 4);
    #pragma unroll
    for (int k4 = 0; k4 < HID / 4; k4++) {
        float4 v = zr[k4];
        z[4*k4+0] = v.x; z[4*k4+1] = v.y; z[4*k4+2] = v.z; z[4*k4+3] = v.w;
    }
    float degf = (float)__ldg(&g_deg[row]);

    float logits[N_CLS];
    #pragma unroll
    for (int cc = 0; cc < N_CLS; cc++) logits[cc] = bfs[cc];

    #pragma unroll 1
    for (int jj = 0; jj < HID / 4; jj++) {
        float h[4];
        #pragma unroll
        for (int u = 0; u < 4; u++) h[u] = degf * b2s[jj * 4 + u];
        #pragma unroll
        for (int k = 0; k < HID; k++) {
            float4 w = *reinterpret_cast<const float4*>(W2s + k * HID + jj * 4);
            h[0] = fmaf(z[k], w.x, h[0]);
            h[1] = fmaf(z[k], w.y, h[1]);
            h[2] = fmaf(z[k], w.z, h[2]);
            h[3] = fmaf(z[k], w.w, h[3]);
        }
        #pragma unroll
        for (int u = 0; u < 4; u++) {
            int j = jj * 4 + u;
            #pragma unroll
            for (int c4 = 0; c4 < N_CLS / 4; c4++) {
                float4 w = *reinterpret_cast<const float4*>(Wfs + j * N_CLS + c4 * 4);
                logits[c4*4+0] = fmaf(h[u], w.x, logits[c4*4+0]);
                logits[c4*4+1] = fmaf(h[u], w.y, logits[c4*4+1]);
                logits[c4*4+2] = fmaf(h[u], w.z, logits[c4*4+2]);
                logits[c4*4+3] = fmaf(h[u], w.w, logits[c4*4+3]);
            }
        }
    }

    float m = logits[0];
    #pragma unroll
    for (int cc = 1; cc < N_CLS; cc++) m = fmaxf(m, logits[cc]);
    float ssum = 0.f;
    #pragma unroll
    for (int cc = 0; cc < N_CLS; cc++) {
        float ev = __expf(logits[cc] - m);
        logits[cc] = ev;
        ssum += ev;
    }
    float inv = 1.f / ssum;
    float* orow = out + (size_t)row * N_CLS;
    #pragma unroll
    for (int c4 = 0; c4 < N_CLS / 4; c4++) {
        float4 o;
        o.x = logits[c4*4+0] * inv; o.y = logits[c4*4+1] * inv;
        o.z = logits[c4*4+2] * inv; o.w = logits[c4*4+3] * inv;
        *reinterpret_cast<float4*>(orow + c4 * 4) = o;
    }
}

// ---------------------------------------------------------------------------
extern "C" void kernel_launch(void* const* d_in, const int* in_sizes, int n_in,
                              void* d_out, int out_size)
{
    const float* nf = (const float*)d_in[0];
    const int*   ei = (const int*)d_in[1];   // int32 (JAX x64 disabled)
    const float* W1 = (const float*)d_in[2];
    const float* b1 = (const float*)d_in[3];
    const float* W2 = (const float*)d_in[4];
    const float* b2 = (const float*)d_in[5];
    const float* Wf = (const float*)d_in[6];
    const float* bf = (const float*)d_in[7];
    float* out = (float*)d_out;

    int n = in_sizes[0] / IN_CH;   // 100000
    int E = in_sizes[1] / 2;       // 1600000

    dense1_kernel<<<(n + 255) / 256, 256>>>(nf, W1, b1, n);  // also zeroes H1/Z/deg

    long long work = (long long)E * 16;
    int sblocks = (int)((work + 255) / 256);
    scatter_kernel<0><<<sblocks, 256>>>(ei, E);
    scatter_kernel<1><<<sblocks, 256>>>(ei, E);

    dense2_kernel<<<(n + 127) / 128, 128>>>(W2, b2, Wf, bf, out, n);
}